// round 10
// baseline (speedup 1.0000x reference)
#include <cuda_runtime.h>

typedef unsigned long long u64;

#define NXg 256
#define NYg 256
#define NCELL (NXg*NYg)
#define TSTEPS 256
#define NSIG 2
#define TR 32            // tile rows (x)
#define TC 16            // tile cols (y)
#define EPP 28           // smem pitch: 2 left guard + 24 + 2 right guard
#define SROWS 42         // 1 top guard + 40 + 1 bottom guard
#define ROW0 1
#define COL0 2
#define NTH 256
#define NBLK 240         // 20 x 12 blocks of 2x2 cells
#define BPR 12
#define TILES_X 8
#define TILES_Y 16
#define NBS (TILES_X*TILES_Y)   // 128 CTAs per signal
#define NB (NSIG*NBS)           // 256 CTAs total, all co-resident (2/SM x 148 SMs)

// Ping-pong magnetization state (only interior band cells ever written/read)
__device__ __align__(16) float g_state[2][NSIG][3*NCELL];
// per-tile monotonic step flags, one 32B sector each (zero-init; monotonic across replays)
__device__ unsigned g_done[NB*8];

// ---- packed f32x2 helpers ----
static __device__ __forceinline__ u64 pk2(float lo, float hi) {
    u64 r; asm("mov.b64 %0,{%1,%2};" : "=l"(r) : "f"(lo), "f"(hi)); return r;
}
static __device__ __forceinline__ void upk2(u64 v, float &lo, float &hi) {
    asm("mov.b64 {%0,%1}, %2;" : "=f"(lo), "=f"(hi) : "l"(v));
}
static __device__ __forceinline__ u64 f2add(u64 a, u64 b) {
    u64 r; asm("add.rn.f32x2 %0,%1,%2;" : "=l"(r) : "l"(a), "l"(b)); return r;
}
static __device__ __forceinline__ u64 f2mul(u64 a, u64 b) {
    u64 r; asm("mul.rn.f32x2 %0,%1,%2;" : "=l"(r) : "l"(a), "l"(b)); return r;
}
static __device__ __forceinline__ u64 f2fma(u64 a, u64 b, u64 c) {
    u64 r; asm("fma.rn.f32x2 %0,%1,%2,%3;" : "=l"(r) : "l"(a), "l"(b), "l"(c)); return r;
}
// ---- gpu-scope acquire/release flag ops ----
static __device__ __forceinline__ unsigned ld_acq(const unsigned* p) {
    unsigned v; asm volatile("ld.acquire.gpu.u32 %0,[%1];" : "=r"(v) : "l"(p) : "memory"); return v;
}
static __device__ __forceinline__ void st_rel(unsigned* p, unsigned v) {
    asm volatile("st.release.gpu.u32 [%0],%1;" :: "l"(p), "r"(v) : "memory");
}

__global__ __launch_bounds__(NTH, 2) void mm_persist_kernel(
    const float* __restrict__ sig,        // (NSIG, TSTEPS, 3)
    const float* __restrict__ Bext,       // (1,3,NX,NY)
    const float* __restrict__ Msat_p,     // scalar
    const int*   __restrict__ src_pos,    // (3,2)
    const int*   __restrict__ probe_pos,  // (5,2)
    float*       __restrict__ out)        // (NSIG, TSTEPS, 5)
{
    __shared__ __align__(16) float stg[2][3][SROWS*EPP];

    const int tid = threadIdx.x;
    const int bid = blockIdx.x;
    const int s    = bid / NBS;
    const int tile = bid % NBS;
    const int tx   = tile / TILES_Y;
    const int ty   = tile % TILES_Y;
    const int ti0  = tx * TR;
    const int tj0  = ty * TC;

    unsigned* myflag = &g_done[bid*8];
    const unsigned base = ld_acq(myflag);   // grid-uniform at entry (monotonic across replays)

    // zero smem once (guard-ring hygiene)
    for (int i = tid; i < 2*3*SROWS*EPP; i += NTH)
        ((float*)stg)[i] = 0.0f;

    const float Msat  = Msat_p[0];
    const float cexch = 7.0e-12f / ((Msat * 5e-8f) * 5e-8f);
    const float cdem  = 1.2566371e-06f * Msat;
    const float alpha = 0.01f;
    const float pref  = -1.0f / (1.0f + alpha*alpha);

    const u64 C_M4   = pk2(-4.0f, -4.0f);
    const u64 C_EXCH = pk2(cexch, cexch);
    const u64 C_NDEM = pk2(-cdem, -cdem);
    const u64 C_NEG1 = pk2(-1.0f, -1.0f);
    const u64 C_PREF = pk2(pref, pref);
    const u64 C_ALPH = pk2(alpha, alpha);
    const u64 C_SOT  = pk2(1.0e-4f, 1.0e-4f);
    const u64 C_TWO  = pk2(2.0f, 2.0f);
    const u64 C_CH   = pk2(0.439875f, 0.439875f);       // 0.5*h
    const u64 C_HH   = pk2(0.87975f, 0.87975f);         // h
    const u64 C_H6   = pk2((float)(0.87975/6.0), (float)(0.87975/6.0));

    const bool active = tid < NBLK;
    const int  br  = tid / BPR;
    const int  bc  = tid - br*BPR;
    const int  li0 = 2*br, lj0 = 2*bc;
    const int  gi0 = ti0 - 4 + li0;
    const int  gj0 = tj0 - 4 + lj0;
    const bool ing = active && gi0 >= 0 && gi0 <= NXg-2 && gj0 >= 0 && gj0 <= NYg-2;
    const bool interior_blk = active && br >= 2 && br < 18 && bc >= 2 && bc < 10;
    const bool deep = br >= 4 && br < 16 && bc >= 4 && bc < 8;
    const bool band = interior_blk && !deep;
    const bool rim  = active && ing && !interior_blk;

    // rim block -> owning neighbor tile flag (each rim block lies in exactly one neighbor)
    const unsigned* nflag = myflag;
    if (rim) {
        int drow = (br < 2) ? -1 : (br >= 18 ? 1 : 0);
        int dcol = (bc < 2) ? -1 : (bc >= 10 ? 1 : 0);
        int ntx = tx + drow, nty = ty + dcol;
        nflag = &g_done[((s*TILES_X + ntx)*TILES_Y + nty)*8];
    }

    const int  B0  = (ROW0 + li0)*EPP + (COL0 + lj0);
    const bool clU = (gi0 == 0), clD = (gi0+1 == NXg-1);
    const bool clL = (gj0 == 0), clR = (gj0+1 == NYg-1);
    const int  iU  = clU ? B0 : B0 - EPP;
    const int  iD  = clD ? B0 + EPP : B0 + 2*EPP;
    const int  iLt = clL ? B0 : B0 - 1;
    const int  iLb = iLt + EPP;
    const int  iRt = clR ? B0 + 1 : B0 + 2;
    const int  iRb = iRt + EPP;
    const int  g0  = gi0*NYg + gj0;

    u64 MR01[3], MR23[3];             // committed m
    u64 M01[3],  M23[3];              // stage m
    u64 A01[3],  A23[3];              // RK accumulators
    u64 BF01x = 0, BF01y = 0, BZ01 = 0;
    u64 BF23x = 0, BF23y = 0, BZ23 = 0;
    u64 BZT01 = 0, BZT23 = 0;
    MR01[0] = 0; MR01[1] = pk2(1.0f, 1.0f); MR01[2] = 0;
    MR23[0] = 0; MR23[1] = pk2(1.0f, 1.0f); MR23[2] = 0;
    int srcf = 0, prf = 0;

    if (ing) {
        int sp[6], pp[10];
        #pragma unroll
        for (int k = 0; k < 6; k++)  sp[k] = src_pos[k];
        #pragma unroll
        for (int k = 0; k < 10; k++) pp[k] = probe_pos[k];
        float2 v;
        v = *(const float2*)&Bext[g0];              BF01x = pk2(v.x, v.y);
        v = *(const float2*)&Bext[g0+NYg];          BF23x = pk2(v.x, v.y);
        v = *(const float2*)&Bext[NCELL+g0];        BF01y = pk2(v.x, v.y);
        v = *(const float2*)&Bext[NCELL+g0+NYg];    BF23y = pk2(v.x, v.y);
        v = *(const float2*)&Bext[2*NCELL+g0];      BZ01  = pk2(v.x, v.y);
        v = *(const float2*)&Bext[2*NCELL+g0+NYg];  BZ23  = pk2(v.x, v.y);
        #pragma unroll
        for (int c = 0; c < 4; c++) {
            int gi = gi0 + (c >> 1), gj = gj0 + (c & 1);
            #pragma unroll
            for (int k = 0; k < 3; k++)
                if (gi == sp[2*k] && gj == sp[2*k+1]) srcf |= (k+1) << (4*c);
            #pragma unroll
            for (int p = 0; p < 5; p++)
                if (gi == pp[2*p] && gj == pp[2*p+1]) prf |= (p+1) << (4*c);
        }
    }

    // initial stg[0] fill (t=0 stage field)
    if (active) {
        #pragma unroll
        for (int X = 0; X < 3; X++) {
            *(u64*)&stg[0][X][B0]     = MR01[X];
            *(u64*)&stg[0][X][B0+EPP] = MR23[X];
        }
    }

    for (int t = 0; t < TSTEPS; t++) {
        const float* __restrict__ bin  = g_state[t & 1][s];
        float*       __restrict__ bout = g_state[(t & 1) ^ 1][s];

        // rim: wait for owning neighbor to finish step t-1, then pull its band (L2)
        if (rim && t > 0) {
            unsigned tgt = base + (unsigned)t;
            while ((int)(ld_acq(nflag) - tgt) < 0) { }
            MR01[0] = __ldcg((const u64*)&bin[g0]);
            MR23[0] = __ldcg((const u64*)&bin[g0+NYg]);
            MR01[1] = __ldcg((const u64*)&bin[NCELL+g0]);
            MR23[1] = __ldcg((const u64*)&bin[NCELL+g0+NYg]);
            MR01[2] = __ldcg((const u64*)&bin[2*NCELL+g0]);
            MR23[2] = __ldcg((const u64*)&bin[2*NCELL+g0+NYg]);
            #pragma unroll
            for (int X = 0; X < 3; X++) {
                *(u64*)&stg[0][X][B0]     = MR01[X];
                *(u64*)&stg[0][X][B0+EPP] = MR23[X];
            }
        }

        if (active) {
            if (srcf) {
                const float* sgp = &sig[(s*TSTEPS + t)*3];
                float sa[4];
                #pragma unroll
                for (int c = 0; c < 4; c++) {
                    int k = (srcf >> (4*c)) & 15;
                    sa[c] = k ? __ldg(&sgp[k-1]) : 0.0f;
                }
                BZT01 = f2add(BZ01, pk2(sa[0], sa[1]));
                BZT23 = f2add(BZ23, pk2(sa[2], sa[3]));
            } else {
                BZT01 = BZ01; BZT23 = BZ23;
            }
            #pragma unroll
            for (int X = 0; X < 3; X++) {
                M01[X] = MR01[X]; M23[X] = MR23[X];
                A01[X] = 0;       A23[X] = 0;
            }
        }
        __syncthreads();

        // One RK4 stage for all blocks (guard-ring garbage never reaches interior).
#define MM_STAGE(CUR, NXT, WISONE, DO_NEXT, C2)                                     \
        if (active) {                                                               \
            u64 LAP01[3], LAP23[3];                                                 \
            _Pragma("unroll")                                                       \
            for (int X = 0; X < 3; X++) {                                           \
                const float* Sp = stg[CUR][X];                                      \
                u64 U01 = *(const u64*)&Sp[iU];                                     \
                u64 D23 = *(const u64*)&Sp[iD];                                     \
                float lt = Sp[iLt], lb = Sp[iLb], rt = Sp[iRt], rb = Sp[iRb];       \
                float m0, m1, m2, m3;                                               \
                upk2(M01[X], m0, m1); upk2(M23[X], m2, m3);                         \
                u64 s01 = f2add(f2add(f2add(U01, M23[X]), pk2(lt, m0)), pk2(m1, rt)); \
                u64 s23 = f2add(f2add(f2add(M01[X], D23), pk2(lb, m2)), pk2(m3, rb)); \
                LAP01[X] = f2fma(M01[X], C_M4, s01);                                \
                LAP23[X] = f2fma(M23[X], C_M4, s23);                                \
            }                                                                       \
            _Pragma("unroll")                                                       \
            for (int P = 0; P < 2; P++) {                                           \
                u64* Mv  = P ? M23  : M01;                                          \
                u64* MRv = P ? MR23 : MR01;                                         \
                u64* Av  = P ? A23  : A01;                                          \
                u64* LAP = P ? LAP23 : LAP01;                                       \
                u64 bfx = P ? BF23x : BF01x;                                        \
                u64 bfy = P ? BF23y : BF01y;                                        \
                u64 bzt = P ? BZT23 : BZT01;                                        \
                u64 bx = f2fma(LAP[0], C_EXCH, bfx);                                \
                u64 by = f2fma(LAP[1], C_EXCH, bfy);                                \
                u64 bz = f2fma(Mv[2], C_NDEM, f2fma(LAP[2], C_EXCH, bzt));          \
                u64 n0 = f2mul(Mv[0], C_NEG1);                                      \
                u64 n1 = f2mul(Mv[1], C_NEG1);                                      \
                u64 n2 = f2mul(Mv[2], C_NEG1);                                      \
                u64 cx = f2fma(Mv[1], bz, f2mul(n2, by));                           \
                u64 cy = f2fma(Mv[2], bx, f2mul(n0, bz));                           \
                u64 cz = f2fma(Mv[0], by, f2mul(n1, bx));                           \
                u64 dx = f2fma(Mv[1], cz, f2mul(n2, cy));                           \
                u64 dy = f2fma(Mv[2], cx, f2mul(n0, cz));                           \
                u64 dz = f2fma(Mv[0], cy, f2mul(n1, cx));                           \
                u64 kx = f2fma(C_SOT, f2mul(Mv[1], Mv[0]),                          \
                               f2mul(C_PREF, f2fma(C_ALPH, dx, cx)));               \
                u64 ky = f2fma(C_SOT, f2fma(n0, Mv[0], f2mul(n2, Mv[2])),           \
                               f2mul(C_PREF, f2fma(C_ALPH, dy, cy)));               \
                u64 kz = f2fma(C_SOT, f2mul(Mv[1], Mv[2]),                          \
                               f2mul(C_PREF, f2fma(C_ALPH, dz, cz)));               \
                if (WISONE) {                                                       \
                    Av[0] = f2add(Av[0], kx);                                       \
                    Av[1] = f2add(Av[1], ky);                                       \
                    Av[2] = f2add(Av[2], kz);                                       \
                } else {                                                            \
                    Av[0] = f2fma(kx, C_TWO, Av[0]);                                \
                    Av[1] = f2fma(ky, C_TWO, Av[1]);                                \
                    Av[2] = f2fma(kz, C_TWO, Av[2]);                                \
                }                                                                   \
                if (DO_NEXT) {                                                      \
                    Mv[0] = f2fma(kx, C2, MRv[0]);                                  \
                    Mv[1] = f2fma(ky, C2, MRv[1]);                                  \
                    Mv[2] = f2fma(kz, C2, MRv[2]);                                  \
                }                                                                   \
            }                                                                       \
            if (DO_NEXT) {                                                          \
                _Pragma("unroll")                                                   \
                for (int X = 0; X < 3; X++) {                                       \
                    *(u64*)&stg[NXT][X][B0]     = M01[X];                           \
                    *(u64*)&stg[NXT][X][B0+EPP] = M23[X];                           \
                }                                                                   \
            }                                                                       \
        }                                                                           \
        if (DO_NEXT) __syncthreads();

        MM_STAGE(0, 1, true,  true,  C_CH)   // k1 -> m + 0.5h k1
        MM_STAGE(1, 0, false, true,  C_CH)   // k2 -> m + 0.5h k2
        MM_STAGE(0, 1, false, true,  C_HH)   // k3 -> m + h   k3
        MM_STAGE(1, 0, true,  false, C_CH)   // k4 (reads stg[1] only; no sync)
#undef MM_STAGE

        // combine; interior stays in regs; stg[0] pre-filled for next step
        if (interior_blk) {
            #pragma unroll
            for (int X = 0; X < 3; X++) {
                MR01[X] = f2fma(A01[X], C_H6, MR01[X]);
                MR23[X] = f2fma(A23[X], C_H6, MR23[X]);
                *(u64*)&stg[0][X][B0]     = MR01[X];
                *(u64*)&stg[0][X][B0+EPP] = MR23[X];
            }
            if (band) {
                __stcg((u64*)&bout[g0],             MR01[0]);
                __stcg((u64*)&bout[g0+NYg],         MR23[0]);
                __stcg((u64*)&bout[NCELL+g0],       MR01[1]);
                __stcg((u64*)&bout[NCELL+g0+NYg],   MR23[1]);
                __stcg((u64*)&bout[2*NCELL+g0],     MR01[2]);
                __stcg((u64*)&bout[2*NCELL+g0+NYg], MR23[2]);
            }
            if (prf) {
                float z0, z1, z2, z3;
                upk2(MR01[2], z0, z1); upk2(MR23[2], z2, z3);
                float zz[4] = {z0, z1, z2, z3};
                #pragma unroll
                for (int c = 0; c < 4; c++) {
                    int p = (prf >> (4*c)) & 15;
                    if (p) out[(s*TSTEPS + t)*5 + (p-1)] = zz[c];
                }
            }
        }

        // post completion of step t to the 8 neighbors (release after band stores)
        __syncthreads();
        if (tid == 0) {
            __threadfence();
            st_rel(myflag, base + (unsigned)(t + 1));
        }
    }
}

extern "C" void kernel_launch(void* const* d_in, const int* in_sizes, int n_in,
                              void* d_out, int out_size) {
    const float* sig       = (const float*)d_in[0];  // (2,256,3)
    const float* Bext      = (const float*)d_in[1];  // (1,3,256,256)
    const float* Msat      = (const float*)d_in[2];  // scalar
    const int*   src_pos   = (const int*)d_in[3];    // (3,2)
    const int*   probe_pos = (const int*)d_in[4];    // (5,2)
    float*       out       = (float*)d_out;          // (2,256,5)

    mm_persist_kernel<<<NB, NTH>>>(sig, Bext, Msat, src_pos, probe_pos, out);
}